// round 5
// baseline (speedup 1.0000x reference)
#include <cuda_runtime.h>
#include <cstdint>

typedef unsigned long long ull;

// ---------- packed f32x2 helpers (Blackwell FFMA2 path, PTX-only) ----------
__device__ __forceinline__ ull fma2(ull a, ull b, ull c) {
    ull d; asm("fma.rn.f32x2 %0, %1, %2, %3;" : "=l"(d) : "l"(a), "l"(b), "l"(c)); return d;
}
__device__ __forceinline__ ull add2(ull a, ull b) {
    ull d; asm("add.rn.f32x2 %0, %1, %2;" : "=l"(d) : "l"(a), "l"(b)); return d;
}
__device__ __forceinline__ ull mul2(ull a, ull b) {
    ull d; asm("mul.rn.f32x2 %0, %1, %2;" : "=l"(d) : "l"(a), "l"(b)); return d;
}
__device__ __forceinline__ ull pk(float lo, float hi) {
    ull r; asm("mov.b64 %0, {%1, %2};" : "=l"(r) : "f"(lo), "f"(hi)); return r;
}
__device__ __forceinline__ void upk(ull v, float& lo, float& hi) {
    asm("mov.b64 {%0, %1}, %2;" : "=f"(lo), "=f"(hi) : "l"(v));
}

// ---------- scratch (device globals: no allocation allowed) ----------
__device__ float g_wt3[1 * 256 * 256];
__device__ float g_wt5[9 * 256 * 256];
__device__ float g_wt7[25 * 256 * 256];
__device__ float g_wtp[1 * 256 * 256];
__device__ float g_q[2048 * 1024];   // [b*256+ch][n]  (channel-major conv output)
__device__ float g_k[2048 * 1024];
__device__ float g_v[2048 * 1024];
__device__ float g_ao[8192 * 256];   // [b*1024+t][ch] (attention output, GEMM-A layout)

// ---------- weight restage: wt[(tap*256+c)*256+o] = w[(o*256+c)*taps + tap] ----------
__global__ void transpose_w(const float* __restrict__ w, float* __restrict__ wt, int taps) {
    int idx = blockIdx.x * 256 + threadIdx.x;     // grid sized exactly taps*256 blocks
    int o = idx & 255;
    int c = (idx >> 8) & 255;
    int t = idx >> 16;
    wt[idx] = w[(o * 256 + c) * taps + t];
}

// ---------- implicit-GEMM conv: C[8192 pix][256 oc] = conv_KS(A) ----------
// tile 128(pix) x 64(oc), BK=16, 256 threads, micro-tile 8x4 in f32x2 pairs.
// TROUT=true  -> write channel-major: C[(b*256+oc)*1024 + n]
// TROUT=false -> write row-major:     C[pix*256 + oc]
template<int KS, bool TROUT>
__global__ __launch_bounds__(256, 2)
void conv_gemm(const float* __restrict__ A, const float* __restrict__ Bt,
               const float* __restrict__ bias, float* __restrict__ C)
{
    __shared__ float As[16][128];
    __shared__ float Bs[16][64];

    const int tid = threadIdx.x;
    const int bn = blockIdx.x;      // 0..3   (oc block of 64)
    const int bm = blockIdx.y;      // 0..63  (pixel block of 128)

    // A-tile loader mapping: 128 pixels x 16 channels
    const int ar = tid >> 1;              // pixel row in tile 0..127
    const int ac = (tid & 1) * 8;         // channel seg 0 or 8
    const int p  = bm * 128 + ar;
    const int pb  = p >> 10;
    const int py0 = (p >> 5) & 31;
    const int px0 = p & 31;

    // B-tile loader mapping: 16 x 64
    const int br = tid >> 4;              // 0..15
    const int bc = (tid & 15) * 4;        // 0..60

    // compute mapping
    const int tx = tid & 15;              // col group: 4 oc
    const int ty = tid >> 4;              // row group: 8 pixels

    ull acc[8][2];
#pragma unroll
    for (int i = 0; i < 8; ++i) { acc[i][0] = 0ull; acc[i][1] = 0ull; }

    const int PAD = KS >> 1;

#pragma unroll 1
    for (int kt = 0; kt < KS * KS; ++kt) {
        const int yy = py0 + kt / KS - PAD;
        const int xx = px0 + kt % KS - PAD;
        const bool valid = ((unsigned)yy < 32u) && ((unsigned)xx < 32u);
        const float* asrc = A + (((pb * 32 + yy) * 32 + xx) << 8) + ac;
        const float* bsrc = Bt + ((kt * 256 + br) << 8) + bn * 64 + bc;

#pragma unroll 1
        for (int ck = 0; ck < 256; ck += 16) {
            float4 a0 = make_float4(0.f, 0.f, 0.f, 0.f), a1 = a0;
            if (valid) {
                a0 = *(const float4*)(asrc + ck);
                a1 = *(const float4*)(asrc + ck + 4);
            }
            float4 b0 = *(const float4*)(bsrc + (ck << 8));

            __syncthreads();   // previous iter's compute done before overwrite
            As[ac + 0][ar] = a0.x; As[ac + 1][ar] = a0.y;
            As[ac + 2][ar] = a0.z; As[ac + 3][ar] = a0.w;
            As[ac + 4][ar] = a1.x; As[ac + 5][ar] = a1.y;
            As[ac + 6][ar] = a1.z; As[ac + 7][ar] = a1.w;
            *(float4*)&Bs[br][bc] = b0;
            __syncthreads();

#pragma unroll
            for (int cc = 0; cc < 16; ++cc) {
                float4 av0 = *(const float4*)&As[cc][ty * 8];
                float4 av1 = *(const float4*)&As[cc][ty * 8 + 4];
                ulonglong2 bv2 = *(const ulonglong2*)&Bs[cc][tx * 4];
                float a[8] = {av0.x, av0.y, av0.z, av0.w, av1.x, av1.y, av1.z, av1.w};
#pragma unroll
                for (int i = 0; i < 8; ++i) {
                    ull a2 = pk(a[i], a[i]);
                    acc[i][0] = fma2(a2, bv2.x, acc[i][0]);
                    acc[i][1] = fma2(a2, bv2.y, acc[i][1]);
                }
            }
        }
    }

    // epilogue
    const int col0 = bn * 64 + tx * 4;
    float bb0 = 0.f, bb1 = 0.f, bb2 = 0.f, bb3 = 0.f;
    if (bias != nullptr) {
        bb0 = bias[col0]; bb1 = bias[col0 + 1]; bb2 = bias[col0 + 2]; bb3 = bias[col0 + 3];
    }
    if (!TROUT) {
#pragma unroll
        for (int i = 0; i < 8; ++i) {
            int row = bm * 128 + ty * 8 + i;
            float x0, x1, x2, x3;
            upk(acc[i][0], x0, x1); upk(acc[i][1], x2, x3);
            *(float4*)(C + (row << 8) + col0) =
                make_float4(x0 + bb0, x1 + bb1, x2 + bb2, x3 + bb3);
        }
    } else {
        const int n0 = ((bm * 128) & 1023) + ty * 8;
        const int bt = (bm * 128) >> 10;   // batch (tile is 128-aligned inside 1024)
        float vals[4][8];
#pragma unroll
        for (int i = 0; i < 8; ++i) {
            float x0, x1, x2, x3;
            upk(acc[i][0], x0, x1); upk(acc[i][1], x2, x3);
            vals[0][i] = x0 + bb0; vals[1][i] = x1 + bb1;
            vals[2][i] = x2 + bb2; vals[3][i] = x3 + bb3;
        }
#pragma unroll
        for (int j = 0; j < 4; ++j) {
            float* dst = C + (((bt * 256 + col0 + j) << 10) + n0);
            *(float4*)(dst)     = make_float4(vals[j][0], vals[j][1], vals[j][2], vals[j][3]);
            *(float4*)(dst + 4) = make_float4(vals[j][4], vals[j][5], vals[j][6], vals[j][7]);
        }
    }
}

// ---------- attention ----------
// The reference's raw reshape means: head a = ch/16, token t = (ch%16)*64 + n/16, dim d = n%16.
// With channel-major conv output, a head slab is contiguous [1024 tokens][16 dims].
// Single-pass softmax using the Cauchy-Schwarz bound M = ||0.25*q|| * max_m ||k_m||  (s - M <= 0).
__global__ __launch_bounds__(512, 1)
void attn_kernel(const float* __restrict__ qT, const float* __restrict__ kT,
                 const float* __restrict__ vT, float* __restrict__ ao)
{
    extern __shared__ float sm[];
    float* Ks = sm;            // [1024][16]
    float* Vs = sm + 16384;    // [1024][16]
    __shared__ int s_maxn;

    const int bh = blockIdx.x;
    const int b = bh >> 4, a = bh & 15;
    const int tid = threadIdx.x;

    const float* kb = kT + ((b * 256 + a * 16) << 10);
    const float* vb = vT + ((b * 256 + a * 16) << 10);
    const float* qslab = qT + ((b * 256 + a * 16) << 10);

    // stage K,V (16384 floats each) — fully coalesced float4 copies
    for (int i = tid; i < 4096; i += 512) {
        ((float4*)Ks)[i] = ((const float4*)kb)[i];
        ((float4*)Vs)[i] = ((const float4*)vb)[i];
    }
    if (tid == 0) s_maxn = 0;
    __syncthreads();

    // max key norm^2 (norms >= 0, so float bits compare monotonically as int)
    float mx = 0.f;
    for (int t = tid; t < 1024; t += 512) {
        const float* kr = Ks + t * 16;
        float s = 0.f;
#pragma unroll
        for (int d = 0; d < 16; ++d) s = fmaf(kr[d], kr[d], s);
        mx = fmaxf(mx, s);
    }
#pragma unroll
    for (int off = 16; off; off >>= 1) mx = fmaxf(mx, __shfl_xor_sync(0xffffffffu, mx, off));
    if ((tid & 31) == 0) atomicMax(&s_maxn, __float_as_int(mx));
    __syncthreads();
    const float kn = sqrtf(__int_as_float(s_maxn));

    for (int qi = 0; qi < 2; ++qi) {
        const int t = qi * 512 + tid;

        ull q2[8];
        {
            const ulonglong2* qp = (const ulonglong2*)(qslab + t * 16);
            ulonglong2 u0 = qp[0], u1 = qp[1], u2 = qp[2], u3 = qp[3];
            q2[0] = u0.x; q2[1] = u0.y; q2[2] = u1.x; q2[3] = u1.y;
            q2[4] = u2.x; q2[5] = u2.y; q2[6] = u3.x; q2[7] = u3.y;
        }
        const ull qs = pk(0.25f, 0.25f);
#pragma unroll
        for (int j = 0; j < 8; ++j) q2[j] = mul2(q2[j], qs);

        // ||q_scaled||
        ull n0 = 0ull, n1 = 0ull;
#pragma unroll
        for (int j = 0; j < 8; j += 2) {
            n0 = fma2(q2[j], q2[j], n0);
            n1 = fma2(q2[j + 1], q2[j + 1], n1);
        }
        n0 = add2(n0, n1);
        float nl, nh; upk(n0, nl, nh);
        const float M = sqrtf(nl + nh) * kn;

        ull acc[8];
#pragma unroll
        for (int j = 0; j < 8; ++j) acc[j] = 0ull;
        float l = 0.f;

#pragma unroll 2
        for (int m = 0; m < 1024; ++m) {
            const ulonglong2* kp = (const ulonglong2*)(Ks + m * 16);
            ulonglong2 k0 = kp[0], k1 = kp[1], k2 = kp[2], k3 = kp[3];
            ull c0 = 0ull, c1 = 0ull;
            c0 = fma2(q2[0], k0.x, c0); c1 = fma2(q2[1], k0.y, c1);
            c0 = fma2(q2[2], k1.x, c0); c1 = fma2(q2[3], k1.y, c1);
            c0 = fma2(q2[4], k2.x, c0); c1 = fma2(q2[5], k2.y, c1);
            c0 = fma2(q2[6], k3.x, c0); c1 = fma2(q2[7], k3.y, c1);
            c0 = add2(c0, c1);
            float sl, sh; upk(c0, sl, sh);
            const float p = __expf(sl + sh - M);   // arg <= 0, no overflow
            l += p;

            const ulonglong2* vp = (const ulonglong2*)(Vs + m * 16);
            ulonglong2 v0 = vp[0], v1 = vp[1], v2 = vp[2], v3 = vp[3];
            const ull pp = pk(p, p);
            acc[0] = fma2(pp, v0.x, acc[0]); acc[1] = fma2(pp, v0.y, acc[1]);
            acc[2] = fma2(pp, v1.x, acc[2]); acc[3] = fma2(pp, v1.y, acc[3]);
            acc[4] = fma2(pp, v2.x, acc[4]); acc[5] = fma2(pp, v2.y, acc[5]);
            acc[6] = fma2(pp, v3.x, acc[6]); acc[7] = fma2(pp, v3.y, acc[7]);
        }

        const float inv = 1.f / l;
        float o[16];
#pragma unroll
        for (int j = 0; j < 8; ++j) upk(acc[j], o[2 * j], o[2 * j + 1]);
        float* dst = ao + (((b << 10) + t) << 8) + a * 16;
#pragma unroll
        for (int cchunk = 0; cchunk < 4; ++cchunk) {
            *(float4*)(dst + cchunk * 4) =
                make_float4(o[cchunk * 4] * inv, o[cchunk * 4 + 1] * inv,
                            o[cchunk * 4 + 2] * inv, o[cchunk * 4 + 3] * inv);
        }
    }
}

// ---------- launch ----------
extern "C" void kernel_launch(void* const* d_in, const int* in_sizes, int n_in,
                              void* d_out, int out_size)
{
    (void)in_sizes; (void)out_size;
    if (n_in < 8) return;

    const float* x  = (const float*)d_in[0];
    const float* w3 = (const float*)d_in[1];
    const float* b3 = (const float*)d_in[2];
    const float* w5 = (const float*)d_in[3];
    const float* b5 = (const float*)d_in[4];
    const float* w7 = (const float*)d_in[5];
    const float* b7 = (const float*)d_in[6];
    const float* wp = (const float*)d_in[7];
    float* out = (float*)d_out;

    float *p_wt3, *p_wt5, *p_wt7, *p_wtp, *p_q, *p_k, *p_v, *p_ao;
    cudaGetSymbolAddress((void**)&p_wt3, g_wt3);
    cudaGetSymbolAddress((void**)&p_wt5, g_wt5);
    cudaGetSymbolAddress((void**)&p_wt7, g_wt7);
    cudaGetSymbolAddress((void**)&p_wtp, g_wtp);
    cudaGetSymbolAddress((void**)&p_q,  g_q);
    cudaGetSymbolAddress((void**)&p_k,  g_k);
    cudaGetSymbolAddress((void**)&p_v,  g_v);
    cudaGetSymbolAddress((void**)&p_ao, g_ao);

    cudaFuncSetAttribute(attn_kernel, cudaFuncAttributeMaxDynamicSharedMemorySize, 131072);

    // weight restage
    transpose_w<<<256, 256>>>(w3, p_wt3, 1);
    transpose_w<<<9 * 256, 256>>>(w5, p_wt5, 9);
    transpose_w<<<25 * 256, 256>>>(w7, p_wt7, 25);
    transpose_w<<<256, 256>>>(wp, p_wtp, 1);

    dim3 grid(4, 64);
    // q: 1x1 (w3), v: 3x3 (w5), k: 5x5 (w7) — names match the reference
    conv_gemm<1, true><<<grid, 256>>>(x, p_wt3, b3, p_q);
    conv_gemm<3, true><<<grid, 256>>>(x, p_wt5, b5, p_v);
    conv_gemm<5, true><<<grid, 256>>>(x, p_wt7, b7, p_k);

    attn_kernel<<<128, 512, 131072>>>(p_q, p_k, p_v, p_ao);

    conv_gemm<1, false><<<grid, 256>>>(p_ao, p_wtp, nullptr, out);
}

// round 6
// speedup vs baseline: 1.0019x; 1.0019x over previous
#include <cuda_runtime.h>
#include <cstdint>

typedef unsigned long long ull;

// ---------- packed f32x2 helpers (Blackwell FFMA2 path, PTX-only) ----------
__device__ __forceinline__ ull fma2(ull a, ull b, ull c) {
    ull d; asm("fma.rn.f32x2 %0, %1, %2, %3;" : "=l"(d) : "l"(a), "l"(b), "l"(c)); return d;
}
__device__ __forceinline__ ull add2(ull a, ull b) {
    ull d; asm("add.rn.f32x2 %0, %1, %2;" : "=l"(d) : "l"(a), "l"(b)); return d;
}
__device__ __forceinline__ ull mul2(ull a, ull b) {
    ull d; asm("mul.rn.f32x2 %0, %1, %2;" : "=l"(d) : "l"(a), "l"(b)); return d;
}
__device__ __forceinline__ ull pk(float lo, float hi) {
    ull r; asm("mov.b64 %0, {%1, %2};" : "=l"(r) : "f"(lo), "f"(hi)); return r;
}
__device__ __forceinline__ void upk(ull v, float& lo, float& hi) {
    asm("mov.b64 {%0, %1}, %2;" : "=f"(lo), "=f"(hi) : "l"(v));
}

// ---------- scratch (device globals: no allocation allowed) ----------
__device__ float g_wt3[1 * 256 * 256];
__device__ float g_wt5[9 * 256 * 256];
__device__ float g_wt7[25 * 256 * 256];
__device__ float g_wtp[1 * 256 * 256];
__device__ float g_q[2048 * 1024];   // [b*256+ch][n]  (channel-major conv output)
__device__ float g_k[2048 * 1024];
__device__ float g_v[2048 * 1024];
__device__ float g_ao[8192 * 256];   // [b*1024+t][ch] (attention output, GEMM-A layout)

// ---------- weight restage: wt[(tap*256+c)*256+o] = w[(o*256+c)*taps + tap] ----------
__global__ void transpose_w(const float* __restrict__ w, float* __restrict__ wt, int taps) {
    int idx = blockIdx.x * 256 + threadIdx.x;     // grid sized exactly taps*256 blocks
    int o = idx & 255;
    int c = (idx >> 8) & 255;
    int t = idx >> 16;
    wt[idx] = w[(o * 256 + c) * taps + t];
}

// ---------- implicit-GEMM conv: C[8192 pix][256 oc] = conv_KS(A) ----------
// tile 128(pix) x 64(oc), BK=16, 256 threads, micro-tile 8x4 in f32x2 pairs.
// TROUT=true  -> write channel-major: C[(b*256+oc)*1024 + n]
// TROUT=false -> write row-major:     C[pix*256 + oc]
template<int KS, bool TROUT>
__global__ __launch_bounds__(256, 2)
void conv_gemm(const float* __restrict__ A, const float* __restrict__ Bt,
               const float* __restrict__ bias, float* __restrict__ C)
{
    __shared__ float As[16][128];
    __shared__ float Bs[16][64];

    const int tid = threadIdx.x;
    const int bn = blockIdx.x;      // 0..3   (oc block of 64)
    const int bm = blockIdx.y;      // 0..63  (pixel block of 128)

    // A-tile loader mapping: 128 pixels x 16 channels
    const int ar = tid >> 1;              // pixel row in tile 0..127
    const int ac = (tid & 1) * 8;         // channel seg 0 or 8
    const int p  = bm * 128 + ar;
    const int pb  = p >> 10;
    const int py0 = (p >> 5) & 31;
    const int px0 = p & 31;

    // B-tile loader mapping: 16 x 64
    const int br = tid >> 4;              // 0..15
    const int bc = (tid & 15) * 4;        // 0..60

    // compute mapping
    const int tx = tid & 15;              // col group: 4 oc
    const int ty = tid >> 4;              // row group: 8 pixels

    ull acc[8][2];
#pragma unroll
    for (int i = 0; i < 8; ++i) { acc[i][0] = 0ull; acc[i][1] = 0ull; }

    const int PAD = KS >> 1;

#pragma unroll 1
    for (int kt = 0; kt < KS * KS; ++kt) {
        const int yy = py0 + kt / KS - PAD;
        const int xx = px0 + kt % KS - PAD;
        const bool valid = ((unsigned)yy < 32u) && ((unsigned)xx < 32u);
        const float* asrc = A + (((pb * 32 + yy) * 32 + xx) << 8) + ac;
        const float* bsrc = Bt + ((kt * 256 + br) << 8) + bn * 64 + bc;

#pragma unroll 1
        for (int ck = 0; ck < 256; ck += 16) {
            float4 a0 = make_float4(0.f, 0.f, 0.f, 0.f), a1 = a0;
            if (valid) {
                a0 = *(const float4*)(asrc + ck);
                a1 = *(const float4*)(asrc + ck + 4);
            }
            float4 b0 = *(const float4*)(bsrc + (ck << 8));

            __syncthreads();   // previous iter's compute done before overwrite
            As[ac + 0][ar] = a0.x; As[ac + 1][ar] = a0.y;
            As[ac + 2][ar] = a0.z; As[ac + 3][ar] = a0.w;
            As[ac + 4][ar] = a1.x; As[ac + 5][ar] = a1.y;
            As[ac + 6][ar] = a1.z; As[ac + 7][ar] = a1.w;
            *(float4*)&Bs[br][bc] = b0;
            __syncthreads();

#pragma unroll
            for (int cc = 0; cc < 16; ++cc) {
                float4 av0 = *(const float4*)&As[cc][ty * 8];
                float4 av1 = *(const float4*)&As[cc][ty * 8 + 4];
                ulonglong2 bv2 = *(const ulonglong2*)&Bs[cc][tx * 4];
                float a[8] = {av0.x, av0.y, av0.z, av0.w, av1.x, av1.y, av1.z, av1.w};
#pragma unroll
                for (int i = 0; i < 8; ++i) {
                    ull a2 = pk(a[i], a[i]);
                    acc[i][0] = fma2(a2, bv2.x, acc[i][0]);
                    acc[i][1] = fma2(a2, bv2.y, acc[i][1]);
                }
            }
        }
    }

    // epilogue
    const int col0 = bn * 64 + tx * 4;
    float bb0 = 0.f, bb1 = 0.f, bb2 = 0.f, bb3 = 0.f;
    if (bias != nullptr) {
        bb0 = bias[col0]; bb1 = bias[col0 + 1]; bb2 = bias[col0 + 2]; bb3 = bias[col0 + 3];
    }
    if (!TROUT) {
#pragma unroll
        for (int i = 0; i < 8; ++i) {
            int row = bm * 128 + ty * 8 + i;
            float x0, x1, x2, x3;
            upk(acc[i][0], x0, x1); upk(acc[i][1], x2, x3);
            *(float4*)(C + (row << 8) + col0) =
                make_float4(x0 + bb0, x1 + bb1, x2 + bb2, x3 + bb3);
        }
    } else {
        const int n0 = ((bm * 128) & 1023) + ty * 8;
        const int bt = (bm * 128) >> 10;   // batch (tile is 128-aligned inside 1024)
        float vals[4][8];
#pragma unroll
        for (int i = 0; i < 8; ++i) {
            float x0, x1, x2, x3;
            upk(acc[i][0], x0, x1); upk(acc[i][1], x2, x3);
            vals[0][i] = x0 + bb0; vals[1][i] = x1 + bb1;
            vals[2][i] = x2 + bb2; vals[3][i] = x3 + bb3;
        }
#pragma unroll
        for (int j = 0; j < 4; ++j) {
            float* dst = C + (((bt * 256 + col0 + j) << 10) + n0);
            *(float4*)(dst)     = make_float4(vals[j][0], vals[j][1], vals[j][2], vals[j][3]);
            *(float4*)(dst + 4) = make_float4(vals[j][4], vals[j][5], vals[j][6], vals[j][7]);
        }
    }
}

// ---------- attention ----------
// The reference's raw reshape means: head a = ch/16, token t = (ch%16)*64 + n/16, dim d = n%16.
// With channel-major conv output, a head slab is contiguous [1024 tokens][16 dims].
// Single-pass softmax using the Cauchy-Schwarz bound M = ||0.25*q|| * max_m ||k_m||  (s - M <= 0).
__global__ __launch_bounds__(512, 1)
void attn_kernel(const float* __restrict__ qT, const float* __restrict__ kT,
                 const float* __restrict__ vT, float* __restrict__ ao)
{
    extern __shared__ float sm[];
    float* Ks = sm;            // [1024][16]
    float* Vs = sm + 16384;    // [1024][16]
    __shared__ int s_maxn;

    const int bh = blockIdx.x;
    const int b = bh >> 4, a = bh & 15;
    const int tid = threadIdx.x;

    const float* kb = kT + ((b * 256 + a * 16) << 10);
    const float* vb = vT + ((b * 256 + a * 16) << 10);
    const float* qslab = qT + ((b * 256 + a * 16) << 10);

    // stage K,V (16384 floats each) — fully coalesced float4 copies
    for (int i = tid; i < 4096; i += 512) {
        ((float4*)Ks)[i] = ((const float4*)kb)[i];
        ((float4*)Vs)[i] = ((const float4*)vb)[i];
    }
    if (tid == 0) s_maxn = 0;
    __syncthreads();

    // max key norm^2 (norms >= 0, so float bits compare monotonically as int)
    float mx = 0.f;
    for (int t = tid; t < 1024; t += 512) {
        const float* kr = Ks + t * 16;
        float s = 0.f;
#pragma unroll
        for (int d = 0; d < 16; ++d) s = fmaf(kr[d], kr[d], s);
        mx = fmaxf(mx, s);
    }
#pragma unroll
    for (int off = 16; off; off >>= 1) mx = fmaxf(mx, __shfl_xor_sync(0xffffffffu, mx, off));
    if ((tid & 31) == 0) atomicMax(&s_maxn, __float_as_int(mx));
    __syncthreads();
    const float kn = sqrtf(__int_as_float(s_maxn));

    for (int qi = 0; qi < 2; ++qi) {
        const int t = qi * 512 + tid;

        ull q2[8];
        {
            const ulonglong2* qp = (const ulonglong2*)(qslab + t * 16);
            ulonglong2 u0 = qp[0], u1 = qp[1], u2 = qp[2], u3 = qp[3];
            q2[0] = u0.x; q2[1] = u0.y; q2[2] = u1.x; q2[3] = u1.y;
            q2[4] = u2.x; q2[5] = u2.y; q2[6] = u3.x; q2[7] = u3.y;
        }
        const ull qs = pk(0.25f, 0.25f);
#pragma unroll
        for (int j = 0; j < 8; ++j) q2[j] = mul2(q2[j], qs);

        // ||q_scaled||
        ull n0 = 0ull, n1 = 0ull;
#pragma unroll
        for (int j = 0; j < 8; j += 2) {
            n0 = fma2(q2[j], q2[j], n0);
            n1 = fma2(q2[j + 1], q2[j + 1], n1);
        }
        n0 = add2(n0, n1);
        float nl, nh; upk(n0, nl, nh);
        const float M = sqrtf(nl + nh) * kn;

        ull acc[8];
#pragma unroll
        for (int j = 0; j < 8; ++j) acc[j] = 0ull;
        float l = 0.f;

#pragma unroll 2
        for (int m = 0; m < 1024; ++m) {
            const ulonglong2* kp = (const ulonglong2*)(Ks + m * 16);
            ulonglong2 k0 = kp[0], k1 = kp[1], k2 = kp[2], k3 = kp[3];
            ull c0 = 0ull, c1 = 0ull;
            c0 = fma2(q2[0], k0.x, c0); c1 = fma2(q2[1], k0.y, c1);
            c0 = fma2(q2[2], k1.x, c0); c1 = fma2(q2[3], k1.y, c1);
            c0 = fma2(q2[4], k2.x, c0); c1 = fma2(q2[5], k2.y, c1);
            c0 = fma2(q2[6], k3.x, c0); c1 = fma2(q2[7], k3.y, c1);
            c0 = add2(c0, c1);
            float sl, sh; upk(c0, sl, sh);
            const float p = __expf(sl + sh - M);   // arg <= 0, no overflow
            l += p;

            const ulonglong2* vp = (const ulonglong2*)(Vs + m * 16);
            ulonglong2 v0 = vp[0], v1 = vp[1], v2 = vp[2], v3 = vp[3];
            const ull pp = pk(p, p);
            acc[0] = fma2(pp, v0.x, acc[0]); acc[1] = fma2(pp, v0.y, acc[1]);
            acc[2] = fma2(pp, v1.x, acc[2]); acc[3] = fma2(pp, v1.y, acc[3]);
            acc[4] = fma2(pp, v2.x, acc[4]); acc[5] = fma2(pp, v2.y, acc[5]);
            acc[6] = fma2(pp, v3.x, acc[6]); acc[7] = fma2(pp, v3.y, acc[7]);
        }

        const float inv = 1.f / l;
        float o[16];
#pragma unroll
        for (int j = 0; j < 8; ++j) upk(acc[j], o[2 * j], o[2 * j + 1]);
        float* dst = ao + (((b << 10) + t) << 8) + a * 16;
#pragma unroll
        for (int cchunk = 0; cchunk < 4; ++cchunk) {
            *(float4*)(dst + cchunk * 4) =
                make_float4(o[cchunk * 4] * inv, o[cchunk * 4 + 1] * inv,
                            o[cchunk * 4 + 2] * inv, o[cchunk * 4 + 3] * inv);
        }
    }
}

// ---------- launch ----------
extern "C" void kernel_launch(void* const* d_in, const int* in_sizes, int n_in,
                              void* d_out, int out_size)
{
    (void)in_sizes; (void)out_size;
    if (n_in < 8) return;

    const float* x  = (const float*)d_in[0];
    const float* w3 = (const float*)d_in[1];
    const float* b3 = (const float*)d_in[2];
    const float* w5 = (const float*)d_in[3];
    const float* b5 = (const float*)d_in[4];
    const float* w7 = (const float*)d_in[5];
    const float* b7 = (const float*)d_in[6];
    const float* wp = (const float*)d_in[7];
    float* out = (float*)d_out;

    float *p_wt3, *p_wt5, *p_wt7, *p_wtp, *p_q, *p_k, *p_v, *p_ao;
    cudaGetSymbolAddress((void**)&p_wt3, g_wt3);
    cudaGetSymbolAddress((void**)&p_wt5, g_wt5);
    cudaGetSymbolAddress((void**)&p_wt7, g_wt7);
    cudaGetSymbolAddress((void**)&p_wtp, g_wtp);
    cudaGetSymbolAddress((void**)&p_q,  g_q);
    cudaGetSymbolAddress((void**)&p_k,  g_k);
    cudaGetSymbolAddress((void**)&p_v,  g_v);
    cudaGetSymbolAddress((void**)&p_ao, g_ao);

    cudaFuncSetAttribute(attn_kernel, cudaFuncAttributeMaxDynamicSharedMemorySize, 131072);

    // weight restage
    transpose_w<<<256, 256>>>(w3, p_wt3, 1);
    transpose_w<<<9 * 256, 256>>>(w5, p_wt5, 9);
    transpose_w<<<25 * 256, 256>>>(w7, p_wt7, 25);
    transpose_w<<<256, 256>>>(wp, p_wtp, 1);

    dim3 grid(4, 64);
    // q: 1x1 (w3), v: 3x3 (w5), k: 5x5 (w7) — names match the reference
    conv_gemm<1, true><<<grid, 256>>>(x, p_wt3, b3, p_q);
    conv_gemm<3, true><<<grid, 256>>>(x, p_wt5, b5, p_v);
    conv_gemm<5, true><<<grid, 256>>>(x, p_wt7, b7, p_k);

    attn_kernel<<<128, 512, 131072>>>(p_q, p_k, p_v, p_ao);

    conv_gemm<1, false><<<grid, 256>>>(p_ao, p_wtp, nullptr, out);
}

// round 9
// speedup vs baseline: 2.0068x; 2.0031x over previous
#include <cuda_runtime.h>
#include <cuda_bf16.h>
#include <cstdint>

typedef unsigned long long ull;

// ---------- packed f32x2 helpers (attention) ----------
__device__ __forceinline__ ull fma2(ull a, ull b, ull c) {
    ull d; asm("fma.rn.f32x2 %0, %1, %2, %3;" : "=l"(d) : "l"(a), "l"(b), "l"(c)); return d;
}
__device__ __forceinline__ ull add2(ull a, ull b) {
    ull d; asm("add.rn.f32x2 %0, %1, %2;" : "=l"(d) : "l"(a), "l"(b)); return d;
}
__device__ __forceinline__ ull mul2(ull a, ull b) {
    ull d; asm("mul.rn.f32x2 %0, %1, %2;" : "=l"(d) : "l"(a), "l"(b)); return d;
}
__device__ __forceinline__ ull pk(float lo, float hi) {
    ull r; asm("mov.b64 %0, {%1, %2};" : "=l"(r) : "f"(lo), "f"(hi)); return r;
}
__device__ __forceinline__ void upk(ull v, float& lo, float& hi) {
    asm("mov.b64 {%0, %1}, %2;" : "=f"(lo), "=f"(hi) : "l"(v));
}

// ---------- warp-MMA primitives (family-portable: no sm_103a-only ISA) ----------
#define SWZ(o) ((uint32_t)(o) ^ ((((uint32_t)(o)) >> 3) & 0x70u))

__device__ __forceinline__ uint32_t smem_u32(const void* p) {
    uint32_t a;
    asm("{ .reg .u64 t; cvta.to.shared.u64 t, %1; cvt.u32.u64 %0, t; }" : "=r"(a) : "l"(p));
    return a;
}
__device__ __forceinline__ void cp16(uint32_t dst, const void* src, uint32_t srcsz) {
    asm volatile("cp.async.ca.shared.global [%0], [%1], 16, %2;"
                 :: "r"(dst), "l"(src), "r"(srcsz) : "memory");
}
#define CP_COMMIT asm volatile("cp.async.commit_group;" ::: "memory")
#define CP_WAIT1  asm volatile("cp.async.wait_group 1;" ::: "memory")
#define CP_WAIT0  asm volatile("cp.async.wait_group 0;" ::: "memory")

#define LDSM4(d, a) \
    asm volatile("ldmatrix.sync.aligned.m8n8.x4.shared.b16 {%0,%1,%2,%3}, [%4];" \
                 : "=r"((d)[0]), "=r"((d)[1]), "=r"((d)[2]), "=r"((d)[3]) : "r"(a))

#define MMA16816(c, a, b0, b1) \
    asm volatile("mma.sync.aligned.m16n8k16.row.col.f32.bf16.bf16.f32 " \
                 "{%0,%1,%2,%3},{%4,%5,%6,%7},{%8,%9},{%0,%1,%2,%3};" \
                 : "+f"((c)[0]), "+f"((c)[1]), "+f"((c)[2]), "+f"((c)[3]) \
                 : "r"((a)[0]), "r"((a)[1]), "r"((a)[2]), "r"((a)[3]), \
                   "r"(b0), "r"(b1))

// ---------- scratch (device globals) ----------
__device__ __align__(128) __nv_bfloat16 g_xh[2097152], g_xl[2097152];     // [pix][256]
__device__ __align__(128) __nv_bfloat16 g_w3h[65536],   g_w3l[65536];     // [tap][oc][cin]
__device__ __align__(128) __nv_bfloat16 g_w5h[589824],  g_w5l[589824];
__device__ __align__(128) __nv_bfloat16 g_w7h[1638400], g_w7l[1638400];
__device__ __align__(128) __nv_bfloat16 g_wph[65536],   g_wpl[65536];
__device__ __align__(128) float g_q[2097152], g_k[2097152], g_v[2097152]; // [b*256+ch][1024]
__device__ __align__(128) __nv_bfloat16 g_aoh[2097152], g_aol[2097152];   // [pix][256]

// ---------- split kernels ----------
__global__ void split_x(const float* __restrict__ x,
                        __nv_bfloat16* __restrict__ xh, __nv_bfloat16* __restrict__ xl) {
    int i = blockIdx.x * 256 + threadIdx.x;
    float f = x[i];
    __nv_bfloat16 h = __float2bfloat16(f);
    xh[i] = h;
    xl[i] = __float2bfloat16(f - __bfloat162float(h));
}
// wt[(tap*256+o)*256+i] = w[(o*256+i)*taps + tap]  (hi/lo split)
__global__ void split_w(const float* __restrict__ w,
                        __nv_bfloat16* __restrict__ wh, __nv_bfloat16* __restrict__ wl,
                        int taps) {
    int idx = blockIdx.x * 256 + threadIdx.x;    // grid = taps*256 blocks
    int o = (idx >> 8) & 255;
    int i = idx & 255;
    int t = idx >> 16;
    float f = w[(o * 256 + i) * taps + t];
    __nv_bfloat16 h = __float2bfloat16(f);
    wh[idx] = h;
    wl[idx] = __float2bfloat16(f - __bfloat162float(h));
}

// ---------- HMMA implicit-GEMM conv ----------
// D[128 pix, 128 oc] = sum over (tap, 64-ch chunk) of 3-term hi/lo bf16 mma.sync.
// SMEM per stage 64KB: Ah@0 Al@16K Bh@32K Bl@48K (SW128 rows of 128B), double buffer.
// 8 warps: warp_m = wid&3 (32 rows), warp_n = wid>>2 (64 cols).
// TROUT=true -> C[(b*256+oc)*1024 + n] (+bias);  else row-major C[pix*256+oc], no bias.
template<int KS, bool TROUT>
__global__ __launch_bounds__(256, 1)
void conv_mma(const __nv_bfloat16* __restrict__ Ah, const __nv_bfloat16* __restrict__ Al,
              const __nv_bfloat16* __restrict__ Bh, const __nv_bfloat16* __restrict__ Bl,
              const float* __restrict__ bias, float* __restrict__ C)
{
    extern __shared__ char smem[];
    const uint32_t sb = smem_u32(smem);
    const int tid = threadIdx.x, wid = tid >> 5, lane = tid & 31;
    const int nb = blockIdx.x;      // oc block of 128 (0..1)
    const int mb = blockIdx.y;      // pixel block of 128 (0..63)
    const int p0 = mb * 128, bimg = p0 >> 10;
    const int wm = (wid & 3) * 32, wn = (wid >> 2) * 64;

    float acc[2][8][4];
#pragma unroll
    for (int mi = 0; mi < 2; ++mi)
#pragma unroll
        for (int n8 = 0; n8 < 8; ++n8)
#pragma unroll
            for (int e = 0; e < 4; ++e) acc[mi][n8][e] = 0.f;

    const int T = KS * KS * 4;      // stages = taps x 4 channel-chunks of 64

    auto stage = [&](int it) {
        const int tap = it >> 2, kc = it & 3;
        const int dy = tap / KS - KS / 2, dx = tap % KS - KS / 2;
        const uint32_t bs = sb + (uint32_t)(it & 1) * 65536u;
#pragma unroll
        for (int pass = 0; pass < 4; ++pass) {
            const int idx = pass * 256 + tid;       // 0..1023
            const int r = idx >> 3, gran = idx & 7; // row 0..127, 16B granule
            const uint32_t so = SWZ(r * 128 + gran * 16);
            // A (pixel row shifted by tap; zfill out-of-image)
            const int p = p0 + r;
            const int py = ((p >> 5) & 31) + dy, px = (p & 31) + dx;
            const bool v = ((unsigned)py < 32u) && ((unsigned)px < 32u);
            const size_t aoff = v ?
                ((size_t)((((bimg * 32 + py) << 5) + px)) * 256 + (size_t)kc * 64) * 2
                + (size_t)gran * 16 : 0;
            const uint32_t sz = v ? 16u : 0u;
            cp16(bs + so,         (const char*)Ah + aoff, sz);
            cp16(bs + 16384 + so, (const char*)Al + aoff, sz);
            // B (always valid)
            const size_t boff =
                ((size_t)(tap * 256 + nb * 128 + r) * 256 + (size_t)kc * 64) * 2
                + (size_t)gran * 16;
            cp16(bs + 32768 + so, (const char*)Bh + boff, 16u);
            cp16(bs + 49152 + so, (const char*)Bl + boff, 16u);
        }
    };

    stage(0); CP_COMMIT;

#pragma unroll 1
    for (int it = 0; it < T; ++it) {
        if (it + 1 < T) { stage(it + 1); CP_COMMIT; CP_WAIT1; }
        else            { CP_WAIT0; }
        __syncthreads();

        const uint32_t bs = sb + (uint32_t)(it & 1) * 65536u;
#pragma unroll
        for (int kk = 0; kk < 4; ++kk) {
            const int kb = kk * 32;                 // 16 bf16 = 32B
            uint32_t ahf[2][4], alf[2][4], bhf[4][4], blf[4][4];
            // A fragments (row-major m16 tiles)
#pragma unroll
            for (int mi = 0; mi < 2; ++mi) {
                const int r = wm + mi * 16 + (lane & 15);
                const int cb = kb + ((lane >> 4) << 4);
                const uint32_t ad = bs + SWZ(r * 128 + cb);
                LDSM4(ahf[mi], ad);
                LDSM4(alf[mi], ad + 16384);
            }
            // B fragments ([n][k] rows = col-major operand), n16 chunks
#pragma unroll
            for (int q = 0; q < 4; ++q) {
                const int r = wn + q * 16 + (lane & 7) + ((lane & 16) >> 1);
                const int cb = kb + ((lane & 8) << 1);
                const uint32_t bd = bs + 32768 + SWZ(r * 128 + cb);
                LDSM4(bhf[q], bd);
                LDSM4(blf[q], bd + 16384);
            }
            // term-major ordering: no back-to-back same-acc dependencies
#pragma unroll
            for (int mi = 0; mi < 2; ++mi)
#pragma unroll
                for (int n8 = 0; n8 < 8; ++n8)
                    MMA16816(acc[mi][n8], ahf[mi],
                             bhf[n8 >> 1][(n8 & 1) * 2], bhf[n8 >> 1][(n8 & 1) * 2 + 1]);
#pragma unroll
            for (int mi = 0; mi < 2; ++mi)
#pragma unroll
                for (int n8 = 0; n8 < 8; ++n8)
                    MMA16816(acc[mi][n8], ahf[mi],
                             blf[n8 >> 1][(n8 & 1) * 2], blf[n8 >> 1][(n8 & 1) * 2 + 1]);
#pragma unroll
            for (int mi = 0; mi < 2; ++mi)
#pragma unroll
                for (int n8 = 0; n8 < 8; ++n8)
                    MMA16816(acc[mi][n8], alf[mi],
                             bhf[n8 >> 1][(n8 & 1) * 2], bhf[n8 >> 1][(n8 & 1) * 2 + 1]);
        }
        __syncthreads();
    }

    // epilogue: D fragment c0=(g,2t) c1=(g,2t+1) c2=(g+8,2t) c3=(g+8,2t+1)
    const int g = lane >> 2, t2 = (lane & 3) * 2;
    if (TROUT) {
#pragma unroll
        for (int mi = 0; mi < 2; ++mi)
#pragma unroll
            for (int n8 = 0; n8 < 8; ++n8) {
                const int c = nb * 128 + wn + n8 * 8 + t2;
                const int r0 = (p0 + wm + mi * 16 + g) & 1023;
                const int r1 = r0 + 8;
                const float b0v = bias[c], b1v = bias[c + 1];
                float* C0 = C + ((size_t)(bimg * 256 + c) << 10);
                float* C1 = C + ((size_t)(bimg * 256 + c + 1) << 10);
                C0[r0] = acc[mi][n8][0] + b0v;
                C1[r0] = acc[mi][n8][1] + b1v;
                C0[r1] = acc[mi][n8][2] + b0v;
                C1[r1] = acc[mi][n8][3] + b1v;
            }
    } else {
#pragma unroll
        for (int mi = 0; mi < 2; ++mi)
#pragma unroll
            for (int n8 = 0; n8 < 8; ++n8) {
                const int c = nb * 128 + wn + n8 * 8 + t2;
                const int r0 = p0 + wm + mi * 16 + g;
                *(float2*)(C + (size_t)r0 * 256 + c) =
                    make_float2(acc[mi][n8][0], acc[mi][n8][1]);
                *(float2*)(C + (size_t)(r0 + 8) * 256 + c) =
                    make_float2(acc[mi][n8][2], acc[mi][n8][3]);
            }
    }
}

// ---------- attention (proven f32x2 path; emits bf16 hi/lo for the MMA linear) ----------
__global__ __launch_bounds__(512, 1)
void attn_kernel(const float* __restrict__ qT, const float* __restrict__ kT,
                 const float* __restrict__ vT,
                 __nv_bfloat16* __restrict__ aoh, __nv_bfloat16* __restrict__ aol)
{
    extern __shared__ float sm[];
    float* Ks = sm;            // [1024][16]
    float* Vs = sm + 16384;    // [1024][16]
    __shared__ int s_maxn;

    const int bh = blockIdx.x;
    const int b = bh >> 4, a = bh & 15;
    const int tid = threadIdx.x;

    const float* kb = kT + ((b * 256 + a * 16) << 10);
    const float* vb = vT + ((b * 256 + a * 16) << 10);
    const float* qslab = qT + ((b * 256 + a * 16) << 10);

    for (int i = tid; i < 4096; i += 512) {
        ((float4*)Ks)[i] = ((const float4*)kb)[i];
        ((float4*)Vs)[i] = ((const float4*)vb)[i];
    }
    if (tid == 0) s_maxn = 0;
    __syncthreads();

    float mx = 0.f;
    for (int t = tid; t < 1024; t += 512) {
        const float* kr = Ks + t * 16;
        float s = 0.f;
#pragma unroll
        for (int d = 0; d < 16; ++d) s = fmaf(kr[d], kr[d], s);
        mx = fmaxf(mx, s);
    }
#pragma unroll
    for (int off = 16; off; off >>= 1) mx = fmaxf(mx, __shfl_xor_sync(0xffffffffu, mx, off));
    if ((tid & 31) == 0) atomicMax(&s_maxn, __float_as_int(mx));
    __syncthreads();
    const float kn = sqrtf(__int_as_float(s_maxn));

    for (int qi = 0; qi < 2; ++qi) {
        const int t = qi * 512 + tid;

        ull q2[8];
        {
            const ulonglong2* qp = (const ulonglong2*)(qslab + t * 16);
            ulonglong2 u0 = qp[0], u1 = qp[1], u2 = qp[2], u3 = qp[3];
            q2[0] = u0.x; q2[1] = u0.y; q2[2] = u1.x; q2[3] = u1.y;
            q2[4] = u2.x; q2[5] = u2.y; q2[6] = u3.x; q2[7] = u3.y;
        }
        const ull qs = pk(0.25f, 0.25f);
#pragma unroll
        for (int j = 0; j < 8; ++j) q2[j] = mul2(q2[j], qs);

        ull n0 = 0ull, n1 = 0ull;
#pragma unroll
        for (int j = 0; j < 8; j += 2) {
            n0 = fma2(q2[j], q2[j], n0);
            n1 = fma2(q2[j + 1], q2[j + 1], n1);
        }
        n0 = add2(n0, n1);
        float nl, nh; upk(n0, nl, nh);
        const float M = sqrtf(nl + nh) * kn;

        ull acc[8];
#pragma unroll
        for (int j = 0; j < 8; ++j) acc[j] = 0ull;
        float l = 0.f;

#pragma unroll 2
        for (int m = 0; m < 1024; ++m) {
            const ulonglong2* kp = (const ulonglong2*)(Ks + m * 16);
            ulonglong2 k0 = kp[0], k1 = kp[1], k2 = kp[2], k3 = kp[3];
            ull c0 = 0ull, c1 = 0ull;
            c0 = fma2(q2[0], k0.x, c0); c1 = fma2(q2[1], k0.y, c1);
            c0 = fma2(q2[2], k1.x, c0); c1 = fma2(q2[3], k1.y, c1);
            c0 = fma2(q2[4], k2.x, c0); c1 = fma2(q2[5], k2.y, c1);
            c0 = fma2(q2[6], k3.x, c0); c1 = fma2(q2[7], k3.y, c1);
            c0 = add2(c0, c1);
            float sl, sh; upk(c0, sl, sh);
            const float p = __expf(sl + sh - M);   // arg <= 0, no overflow
            l += p;

            const ulonglong2* vp = (const ulonglong2*)(Vs + m * 16);
            ulonglong2 v0 = vp[0], v1 = vp[1], v2 = vp[2], v3 = vp[3];
            const ull pp = pk(p, p);
            acc[0] = fma2(pp, v0.x, acc[0]); acc[1] = fma2(pp, v0.y, acc[1]);
            acc[2] = fma2(pp, v1.x, acc[2]); acc[3] = fma2(pp, v1.y, acc[3]);
            acc[4] = fma2(pp, v2.x, acc[4]); acc[5] = fma2(pp, v2.y, acc[5]);
            acc[6] = fma2(pp, v3.x, acc[6]); acc[7] = fma2(pp, v3.y, acc[7]);
        }

        const float inv = 1.f / l;
        float o[16];
#pragma unroll
        for (int j = 0; j < 8; ++j) upk(acc[j], o[2 * j], o[2 * j + 1]);
        const size_t base = ((size_t)((b << 10) + t)) * 256 + a * 16;
        __nv_bfloat162* dh = (__nv_bfloat162*)(aoh + base);
        __nv_bfloat162* dl = (__nv_bfloat162*)(aol + base);
#pragma unroll
        for (int j = 0; j < 8; ++j) {
            float v0 = o[2 * j] * inv, v1 = o[2 * j + 1] * inv;
            __nv_bfloat16 h0 = __float2bfloat16(v0), h1 = __float2bfloat16(v1);
            __nv_bfloat16 l0 = __float2bfloat16(v0 - __bfloat162float(h0));
            __nv_bfloat16 l1 = __float2bfloat16(v1 - __bfloat162float(h1));
            dh[j] = __halves2bfloat162(h0, h1);
            dl[j] = __halves2bfloat162(l0, l1);
        }
    }
}

// ---------- launch ----------
extern "C" void kernel_launch(void* const* d_in, const int* in_sizes, int n_in,
                              void* d_out, int out_size)
{
    (void)in_sizes; (void)out_size;
    if (n_in < 8) return;

    const float* x  = (const float*)d_in[0];
    const float* w3 = (const float*)d_in[1];
    const float* b3 = (const float*)d_in[2];
    const float* w5 = (const float*)d_in[3];
    const float* b5 = (const float*)d_in[4];
    const float* w7 = (const float*)d_in[5];
    const float* b7 = (const float*)d_in[6];
    const float* wp = (const float*)d_in[7];
    float* out = (float*)d_out;

    __nv_bfloat16 *p_xh, *p_xl, *p_w3h, *p_w3l, *p_w5h, *p_w5l, *p_w7h, *p_w7l,
                  *p_wph, *p_wpl, *p_aoh, *p_aol;
    float *p_q, *p_k, *p_v;
    cudaGetSymbolAddress((void**)&p_xh,  g_xh);  cudaGetSymbolAddress((void**)&p_xl,  g_xl);
    cudaGetSymbolAddress((void**)&p_w3h, g_w3h); cudaGetSymbolAddress((void**)&p_w3l, g_w3l);
    cudaGetSymbolAddress((void**)&p_w5h, g_w5h); cudaGetSymbolAddress((void**)&p_w5l, g_w5l);
    cudaGetSymbolAddress((void**)&p_w7h, g_w7h); cudaGetSymbolAddress((void**)&p_w7l, g_w7l);
    cudaGetSymbolAddress((void**)&p_wph, g_wph); cudaGetSymbolAddress((void**)&p_wpl, g_wpl);
    cudaGetSymbolAddress((void**)&p_aoh, g_aoh); cudaGetSymbolAddress((void**)&p_aol, g_aol);
    cudaGetSymbolAddress((void**)&p_q, g_q);
    cudaGetSymbolAddress((void**)&p_k, g_k);
    cudaGetSymbolAddress((void**)&p_v, g_v);

    const int CONV_SMEM = 2 * 65536;   // 128 KB (double-buffered stages)
    cudaFuncSetAttribute(conv_mma<1, true>,  cudaFuncAttributeMaxDynamicSharedMemorySize, CONV_SMEM);
    cudaFuncSetAttribute(conv_mma<3, true>,  cudaFuncAttributeMaxDynamicSharedMemorySize, CONV_SMEM);
    cudaFuncSetAttribute(conv_mma<5, true>,  cudaFuncAttributeMaxDynamicSharedMemorySize, CONV_SMEM);
    cudaFuncSetAttribute(conv_mma<1, false>, cudaFuncAttributeMaxDynamicSharedMemorySize, CONV_SMEM);
    cudaFuncSetAttribute(attn_kernel, cudaFuncAttributeMaxDynamicSharedMemorySize, 131072);

    // hi/lo splits
    split_x<<<8192, 256>>>(x, p_xh, p_xl);
    split_w<<<1 * 256, 256>>>(w3, p_w3h, p_w3l, 1);
    split_w<<<9 * 256, 256>>>(w5, p_w5h, p_w5l, 9);
    split_w<<<25 * 256, 256>>>(w7, p_w7h, p_w7l, 25);
    split_w<<<1 * 256, 256>>>(wp, p_wph, p_wpl, 1);

    dim3 grid(2, 64);
    // q: 1x1 (w3), v: 3x3 (w5), k: 5x5 (w7) — names match the reference
    conv_mma<1, true><<<grid, 256, CONV_SMEM>>>(p_xh, p_xl, p_w3h, p_w3l, b3, p_q);
    conv_mma<3, true><<<grid, 256, CONV_SMEM>>>(p_xh, p_xl, p_w5h, p_w5l, b5, p_v);
    conv_mma<5, true><<<grid, 256, CONV_SMEM>>>(p_xh, p_xl, p_w7h, p_w7l, b7, p_k);

    attn_kernel<<<128, 512, 131072>>>(p_q, p_k, p_v, p_aoh, p_aol);

    conv_mma<1, false><<<grid, 256, CONV_SMEM>>>(p_aoh, p_aol, p_wph, p_wpl, nullptr, out);
}